// round 7
// baseline (speedup 1.0000x reference)
#include <cuda_runtime.h>
#include <cuda_fp16.h>
#include <cstdint>

typedef unsigned long long u64;
typedef unsigned int u32;

#define NPTS    6144
#define JSPLIT  24
#define IBLK    (NPTS / 256)          // 24 i-blocks (256 rows each)
#define KSPB    16                    // k-steps per block (16 j each -> 256 j)
#define NMOM    24                    // moment columns (21 used)

// ---------------- device scratch ----------------
__device__ float g_part[JSPLIT * NPTS * NMOM];   // ~14 MB, L2-resident
__device__ u32   g_cnt[IBLK];                    // zero-init; restored to 0 each replay

// ---------------- helpers ----------------
__device__ __forceinline__ u64 pk2(float lo, float hi) {
    u64 r; asm("mov.b64 %0, {%1, %2};" : "=l"(r) : "f"(lo), "f"(hi)); return r;
}
__device__ __forceinline__ void upk2(u64 v, float& lo, float& hi) {
    asm("mov.b64 {%0, %1}, %2;" : "=f"(lo), "=f"(hi) : "l"(v));
}
__device__ __forceinline__ u64 fma2(u64 a, u64 b, u64 c) {
    u64 d; asm("fma.rn.f32x2 %0, %1, %2, %3;" : "=l"(d) : "l"(a), "l"(b), "l"(c)); return d;
}
__device__ __forceinline__ float ex2f(float a) {
    float r; asm("ex2.approx.ftz.f32 %0, %1;" : "=f"(r) : "f"(a)); return r;
}
// pack two f32 -> f16x2 (first arg in low 16 bits)
__device__ __forceinline__ u32 f16pk(float lo, float hi) {
    u32 d; asm("cvt.rn.f16x2.f32 %0, %1, %2;" : "=r"(d) : "f"(hi), "f"(lo)); return d;
}
__device__ __forceinline__ void mma_f16(float* c, const u32* a, const u32* b) {
    asm volatile(
        "mma.sync.aligned.m16n8k16.row.col.f32.f16.f16.f32 "
        "{%0,%1,%2,%3}, {%4,%5,%6,%7}, {%8,%9}, {%0,%1,%2,%3};"
        : "+f"(c[0]), "+f"(c[1]), "+f"(c[2]), "+f"(c[3])
        : "r"(a[0]), "r"(a[1]), "r"(a[2]), "r"(a[3]), "r"(b[0]), "r"(b[1]));
}

// ---------------- single fused kernel ----------------
__global__ __launch_bounds__(256, 2) void rbf_fused(
    const float* __restrict__ x,  const float* __restrict__ z,
    const float* __restrict__ t,  const float* __restrict__ c,
    const float* __restrict__ v1, const float* __restrict__ v2,
    const float* __restrict__ v3, const float* __restrict__ v4,
    float* __restrict__ out)
{
    __shared__ float scx[256], scz[256], sct[256];
    __shared__ float sv[4][256];
    __shared__ __align__(16) u64 sC[256 * 4];        // 8 KB  A-side constants per j
    __shared__ __align__(16) u64 sF[KSPB * 192];     // 24 KB fp16 B fragments
    __shared__ int s_last;

    const int tid  = threadIdx.x;
    const int w    = tid >> 5, lane = tid & 31;
    const int r    = lane >> 2, cc = lane & 3;
    const int ib   = blockIdx.x, js = blockIdx.y;
    const int i0   = ib * 256 + w * 32;
    const int j0   = js * 256;

    // ---------- phase A0: coalesced stage of raw inputs ----------
    for (int q = tid; q < 768; q += 256) {
        const float val = c[j0 * 3 + q];
        const int j = q / 3, rr = q - 3 * j;
        if (rr == 0) scx[j] = val; else if (rr == 1) scz[j] = val; else sct[j] = val;
    }
    for (int q = tid; q < 1024; q += 256) {
        const int vi = q >> 8, jj = q & 255;
        const float* vp = (vi == 0) ? v1 : (vi == 1) ? v2 : (vi == 2) ? v3 : v4;
        sv[vi][jj] = vp[j0 + jj];
    }
    __syncthreads();

    // ---------- phase A1: A-side constants (one j per thread) ----------
    {
        const float L2E = 1.4426950408889634f;
        const float cx = scx[tid], cz = scz[tid], ct = sct[tid];
        const float kc = -0.5f * (cx * cx + cz * cz + ct * ct) * L2E;
        sC[tid * 4 + 0] = pk2(cx * L2E, cx * L2E);
        sC[tid * 4 + 1] = pk2(cz * L2E, cz * L2E);
        sC[tid * 4 + 2] = pk2(ct * L2E, ct * L2E);
        sC[tid * 4 + 3] = pk2(kc, kc);
    }

    // ---------- phase A2: fp16 hi/lo B fragments (1536 tasks) ----------
#pragma unroll
    for (int it = 0; it < 6; it++) {
        const int task = it * 256 + tid;
        const int lt   = task & 31;
        const int n    = (task >> 5) % 3;
        const int ksl  = task / 96;
        const int cct  = lt & 3, gt = lt >> 2;
        const int m    = n * 8 + gt;

        float u[4];
#pragma unroll
        for (int q = 0; q < 4; q++) {
            const int jl = ksl * 16 + 2 * cct + (q & 1) + ((q >> 1) << 3);
            float val = 0.0f;
            if (m < 21) {
                const float cx = scx[jl], cz = scz[jl], ct = sct[jl];
                float vv, base;
                int r6;
                if (m < 3) { vv = sv[0][jl]; r6 = m; }
                else {
                    const int g2 = (m - 3) / 6;
                    vv = sv[1 + g2][jl];
                    r6 = (m - 3) % 6;
                }
                base = (r6 == 0) ? 1.0f : (r6 == 1) ? cx : (r6 == 2) ? cz :
                       (r6 == 3) ? ct   : (r6 == 4) ? cx * cx : cz * cz;
                val = base * vv;
            }
            u[q] = val;
        }
        const u32 b0h = f16pk(u[0], u[1]);
        const u32 b1h = f16pk(u[2], u[3]);
        const float h00 = __half2float(__ushort_as_half((unsigned short)(b0h & 0xFFFFu)));
        const float h01 = __half2float(__ushort_as_half((unsigned short)(b0h >> 16)));
        const float h10 = __half2float(__ushort_as_half((unsigned short)(b1h & 0xFFFFu)));
        const float h11 = __half2float(__ushort_as_half((unsigned short)(b1h >> 16)));
        const u32 b0l = f16pk(u[0] - h00, u[1] - h01);
        const u32 b1l = f16pk(u[2] - h10, u[3] - h11);
        sF[ksl * 192 +  0 + n * 32 + lt] = ((u64)b1h << 32) | b0h;   // hi term
        sF[ksl * 192 + 96 + n * 32 + lt] = ((u64)b1l << 32) | b0l;   // lo term
    }

    // row coordinates (overlap loads with phase A)
    const u64 xp0 = pk2(x[i0 + r], x[i0 + r + 8]);
    const u64 xp1 = pk2(x[i0 + r + 16], x[i0 + r + 24]);
    const u64 zp0 = pk2(z[i0 + r], z[i0 + r + 8]);
    const u64 zp1 = pk2(z[i0 + r + 16], z[i0 + r + 24]);
    const u64 tp0 = pk2(t[i0 + r], t[i0 + r + 8]);
    const u64 tp1 = pk2(t[i0 + r + 16], t[i0 + r + 24]);

    float acc[2][3][4];
#pragma unroll
    for (int a = 0; a < 2; a++)
#pragma unroll
        for (int b = 0; b < 3; b++)
#pragma unroll
            for (int q = 0; q < 4; q++) acc[a][b][q] = 0.0f;

    __syncthreads();

    // ---------- phase B: main loop (all smem read-only, no syncs) ----------
#pragma unroll 1
    for (int k = 0; k < KSPB; k++) {
        float G0[4], G1[4], G2[4], G3[4];
#pragma unroll
        for (int jj = 0; jj < 4; jj++) {
            const int jloc = 2 * cc + (jj & 1) + ((jj >> 1) << 3);
            const char* cp = (const char*)sC + k * 512 + jloc * 32;
            const ulonglong2 q0 = *(const ulonglong2*)cp;
            const ulonglong2 q1 = *(const ulonglong2*)(cp + 16);
            u64 d0 = fma2(q1.x, tp0, q1.y);
            d0 = fma2(q0.y, zp0, d0);
            d0 = fma2(q0.x, xp0, d0);
            u64 d1 = fma2(q1.x, tp1, q1.y);
            d1 = fma2(q0.y, zp1, d1);
            d1 = fma2(q0.x, xp1, d1);
            float f0, f1, f2, f3; upk2(d0, f0, f1); upk2(d1, f2, f3);
            G0[jj] = ex2f(f0); G1[jj] = ex2f(f1);
            G2[jj] = ex2f(f2); G3[jj] = ex2f(f3);
        }
        u32 ah[2][4];
        ah[0][0] = f16pk(G0[0], G0[1]);
        ah[0][1] = f16pk(G1[0], G1[1]);
        ah[0][2] = f16pk(G0[2], G0[3]);
        ah[0][3] = f16pk(G1[2], G1[3]);
        ah[1][0] = f16pk(G2[0], G2[1]);
        ah[1][1] = f16pk(G3[0], G3[1]);
        ah[1][2] = f16pk(G2[2], G2[3]);
        ah[1][3] = f16pk(G3[2], G3[3]);

        u32 bh[3][2], bl[3][2];
        const char* bp = (const char*)sF + k * 1536 + lane * 8;
#pragma unroll
        for (int n = 0; n < 3; n++) {
            const uint2 vh = *(const uint2*)(bp + n * 256);
            const uint2 vl = *(const uint2*)(bp + 768 + n * 256);
            bh[n][0] = vh.x; bh[n][1] = vh.y;
            bl[n][0] = vl.x; bl[n][1] = vl.y;
        }

#pragma unroll
        for (int mt = 0; mt < 2; mt++)
#pragma unroll
            for (int n = 0; n < 3; n++) {
                mma_f16(acc[mt][n], ah[mt], bh[n]);
                mma_f16(acc[mt][n], ah[mt], bl[n]);
            }
    }

    // ---------- write moment partials ----------
#pragma unroll
    for (int mt = 0; mt < 2; mt++)
#pragma unroll
        for (int n = 0; n < 3; n++) {
            const int row = i0 + mt * 16 + r;
            const int col = n * 8 + 2 * cc;
            float2* d0 = (float2*)&g_part[((u64)js * NPTS + row) * NMOM + col];
            float2* d1 = (float2*)&g_part[((u64)js * NPTS + row + 8) * NMOM + col];
            *d0 = make_float2(acc[mt][n][0], acc[mt][n][1]);
            *d1 = make_float2(acc[mt][n][2], acc[mt][n][3]);
        }

    // ---------- phase C: last block of this i-group does the epilogue ----------
    __threadfence();
    __syncthreads();
    if (tid == 0) {
        const u32 old = atomicAdd(&g_cnt[ib], 1u);
        s_last = (old == JSPLIT - 1);
    }
    __syncthreads();
    if (!s_last) return;

    __threadfence();   // acquire: all groups' partials now visible
    {
        const int i = ib * 256 + tid;
        float S[NMOM];
#pragma unroll
        for (int m = 0; m < NMOM; m++) S[m] = 0.0f;
#pragma unroll 4
        for (int jq = 0; jq < JSPLIT; jq++) {
            const float4* p = (const float4*)&g_part[((u64)jq * NPTS + i) * NMOM];
#pragma unroll
            for (int q = 0; q < 6; q++) {
                const float4 v = p[q];
                S[q * 4 + 0] += v.x; S[q * 4 + 1] += v.y;
                S[q * 4 + 2] += v.z; S[q * 4 + 3] += v.w;
            }
        }
        const float xi = x[i], zi = z[i], ti = t[i];
        const float ep = __expf(-0.5f * (xi * xi + zi * zi + ti * ti));
#pragma unroll
        for (int m = 0; m < 21; m++) S[m] *= ep;
        const float xx = xi * xi - 1.0f, zz = zi * zi - 1.0f;

        out[0  * NPTS + i] = S[10] - xi * S[9];
        out[1  * NPTS + i] = S[11] - zi * S[9];
        out[2  * NPTS + i] = S[12] - ti * S[9];
        out[3  * NPTS + i] = S[16] - xi * S[15];
        out[4  * NPTS + i] = S[17] - zi * S[15];
        out[5  * NPTS + i] = S[18] - ti * S[15];
        out[6  * NPTS + i] = S[4]  - xi * S[3];
        out[7  * NPTS + i] = S[5]  - zi * S[3];
        out[8  * NPTS + i] = S[6]  - ti * S[3];
        out[9  * NPTS + i] = S[1]  - xi * S[0];
        out[10 * NPTS + i] = S[2]  - zi * S[0];
        out[11 * NPTS + i] = S[13] - 2.0f * xi * S[10] + xx * S[9];
        out[12 * NPTS + i] = S[14] - 2.0f * zi * S[11] + zz * S[9];
        out[13 * NPTS + i] = S[19] - 2.0f * xi * S[16] + xx * S[15];
        out[14 * NPTS + i] = S[20] - 2.0f * zi * S[17] + zz * S[15];
        out[15 * NPTS + i] = S[7]  - 2.0f * xi * S[4]  + xx * S[3];
        out[16 * NPTS + i] = S[8]  - 2.0f * zi * S[5]  + zz * S[3];
    }
    __syncthreads();
    if (tid == 0) atomicExch(&g_cnt[ib], 0u);   // restore for next graph replay
}

extern "C" void kernel_launch(void* const* d_in, const int* in_sizes, int n_in,
                              void* d_out, int out_size)
{
    const float* x  = (const float*)d_in[0];
    const float* z  = (const float*)d_in[1];
    const float* t  = (const float*)d_in[2];
    const float* c  = (const float*)d_in[3];
    const float* v1 = (const float*)d_in[4];
    const float* v2 = (const float*)d_in[5];
    const float* v3 = (const float*)d_in[6];
    const float* v4 = (const float*)d_in[7];

    dim3 grid(IBLK, JSPLIT);   // (24, 24) = 576 blocks, one single launch
    rbf_fused<<<grid, 256>>>(x, z, t, c, v1, v2, v3, v4, (float*)d_out);
}

// round 8
// speedup vs baseline: 1.8119x; 1.8119x over previous
#include <cuda_runtime.h>
#include <cuda_fp16.h>
#include <cstdint>

typedef unsigned long long u64;
typedef unsigned int u32;

#define NPTS    6144
#define JSPLIT  12
#define IBLK    (NPTS / 256)          // 24 i-blocks (256 rows each)
#define KSTEPS  (NPTS / 16)           // 384 total k-steps (16 j each)
#define KSPB    (KSTEPS / JSPLIT)     // 32 k-steps per block
#define KS_STAGE 8
#define NSTAGE  (KSPB / KS_STAGE)     // 4
#define NMOM    24                    // moment columns (21 used)

// ---------------- device scratch ----------------
// arg-GEMM B fragments: per ks, 32 lanes x 16B = 512B
__device__ u32 g_Af[KSTEPS * 128];
// moment B fragments: [ks][term(hi/lo)][n(0..2)][lane] u64
__device__ u64 g_Bf[KSTEPS * 2 * 3 * 32];
// moment partials: [JSPLIT][NPTS][NMOM]
__device__ float g_part[JSPLIT * NPTS * NMOM];
__device__ u32 g_cnt[IBLK];          // zero-init; restored each call

// ---------------- helpers ----------------
__device__ __forceinline__ u32 smem_u32(const void* p) {
    u32 a; asm("{ .reg .u64 t; cvta.to.shared.u64 t, %1; cvt.u32.u64 %0, t; }" : "=r"(a) : "l"(p));
    return a;
}
__device__ __forceinline__ float ex2f(float a) {
    float r; asm("ex2.approx.ftz.f32 %0, %1;" : "=f"(r) : "f"(a)); return r;
}
// pack two f32 -> f16x2 (first arg in LOW 16 bits)
__device__ __forceinline__ u32 f16pk(float lo, float hi) {
    u32 d; asm("cvt.rn.f16x2.f32 %0, %1, %2;" : "=r"(d) : "f"(hi), "f"(lo)); return d;
}
__device__ __forceinline__ void cpa16(u32 saddr, const void* g) {
    asm volatile("cp.async.cg.shared.global [%0], [%1], 16;" :: "r"(saddr), "l"(g));
}
__device__ __forceinline__ void cpa_commit() { asm volatile("cp.async.commit_group;" ::: "memory"); }
template <int N> __device__ __forceinline__ void cpa_wait() {
    asm volatile("cp.async.wait_group %0;" :: "n"(N) : "memory");
}
__device__ __forceinline__ void mma_f16(float* c, const u32* a, const u32* b) {
    asm volatile(
        "mma.sync.aligned.m16n8k16.row.col.f32.f16.f16.f32 "
        "{%0,%1,%2,%3}, {%4,%5,%6,%7}, {%8,%9}, {%0,%1,%2,%3};"
        : "+f"(c[0]), "+f"(c[1]), "+f"(c[2]), "+f"(c[3])
        : "r"(a[0]), "r"(a[1]), "r"(a[2]), "r"(a[3]), "r"(b[0]), "r"(b[1]));
}

// ---------------- prep: arg fragments + moment fragments ----------------
__global__ void prep_all(const float* __restrict__ c,
                         const float* __restrict__ v1, const float* __restrict__ v2,
                         const float* __restrict__ v3, const float* __restrict__ v4)
{
    const int idx = blockIdx.x * blockDim.x + threadIdx.x;
    const float L2E = 1.4426950408889634f;

    // ---- part 1: arg-GEMM B fragments (KSTEPS*32 tasks) ----
    // P-row (A side) = [xh,xl,zh,zl,th,tl,xh,zh,th,1,1,0,...]; B col per j:
    // k0,k1=Cxh,Cxh  k2,k3=Czh,Czh  k4,k5=Cth,Cth  k6,k7=Cxl,Czl  k8=Ctl k9=kch k10=kcl
    if (idx < KSTEPS * 32) {
        const int lane = idx & 31, ks = idx >> 5;
        const int tc = lane & 3, gr = lane >> 2;
#pragma unroll
        for (int half = 0; half < 2; half++) {
            const int j = ks * 16 + half * 8 + gr;
            const float cx = c[3 * j], cz = c[3 * j + 1], ct = c[3 * j + 2];
            const float Cx = cx * L2E, Cz = cz * L2E, Ct = ct * L2E;
            const float kc = -0.5f * (cx * cx + cz * cz + ct * ct) * L2E;
            const float Cxh = __half2float(__float2half_rn(Cx)), Cxl = Cx - Cxh;
            const float Czh = __half2float(__float2half_rn(Cz)), Czl = Cz - Czh;
            const float Cth = __half2float(__float2half_rn(Ct)), Ctl = Ct - Cth;
            const float kch = __half2float(__float2half_rn(kc)), kcl = kc - kch;
            u32 b0, b1;
            if (tc == 0)      { b0 = f16pk(Cxh, Cxh); b1 = f16pk(Ctl, kch); }
            else if (tc == 1) { b0 = f16pk(Czh, Czh); b1 = f16pk(kcl, 0.f); }
            else if (tc == 2) { b0 = f16pk(Cth, Cth); b1 = 0u; }
            else              { b0 = f16pk(Cxl, Czl); b1 = 0u; }
            g_Af[ks * 128 + lane * 4 + half * 2 + 0] = b0;
            g_Af[ks * 128 + lane * 4 + half * 2 + 1] = b1;
        }
    }

    // ---- part 2: moment B fragments (KSTEPS*96 tasks) ----
    if (idx < KSTEPS * 96) {
        const int lane = idx & 31;
        const int n    = (idx >> 5) % 3;
        const int ks   = idx / 96;
        const int tc   = lane & 3, gr = lane >> 2;
        const int m    = n * 8 + gr;

        float u[4];
#pragma unroll
        for (int q = 0; q < 4; q++) {
            const int j = ks * 16 + 2 * tc + (q & 1) + ((q >> 1) << 3);
            float val = 0.0f;
            if (m < 21) {
                const float cx = c[3 * j], cz = c[3 * j + 1], ct = c[3 * j + 2];
                float vv, base;
                int r6;
                if (m < 3) { vv = v1[j]; r6 = m; }
                else {
                    const int g2 = (m - 3) / 6;
                    vv = (g2 == 0) ? v2[j] : (g2 == 1) ? v3[j] : v4[j];
                    r6 = (m - 3) % 6;
                }
                base = (r6 == 0) ? 1.0f : (r6 == 1) ? cx : (r6 == 2) ? cz :
                       (r6 == 3) ? ct   : (r6 == 4) ? cx * cx : cz * cz;
                val = base * vv;
            }
            u[q] = val;
        }
        const u32 b0h = f16pk(u[0], u[1]);
        const u32 b1h = f16pk(u[2], u[3]);
        const float h00 = __half2float(__ushort_as_half((unsigned short)(b0h & 0xFFFFu)));
        const float h01 = __half2float(__ushort_as_half((unsigned short)(b0h >> 16)));
        const float h10 = __half2float(__ushort_as_half((unsigned short)(b1h & 0xFFFFu)));
        const float h11 = __half2float(__ushort_as_half((unsigned short)(b1h >> 16)));
        const u32 b0l = f16pk(u[0] - h00, u[1] - h01);
        const u32 b1l = f16pk(u[2] - h10, u[3] - h11);
        g_Bf[(ks * 2 + 0) * 96 + n * 32 + lane] = ((u64)b1h << 32) | b0h;
        g_Bf[(ks * 2 + 1) * 96 + n * 32 + lane] = ((u64)b1l << 32) | b0l;
    }
}

// ---------------- main: arg-GEMM -> ex2 -> moment GEMM, fused epilogue ----------------
__global__ __launch_bounds__(256, 2) void rbf_mma(
    const float* __restrict__ x, const float* __restrict__ z, const float* __restrict__ t,
    float* __restrict__ out)
{
    __shared__ __align__(16) char sB[2][KS_STAGE * 1536];   // 2 x 12KB moment frags
    __shared__ __align__(16) char sA[2][KS_STAGE * 512];    // 2 x 4KB  arg frags
    __shared__ int s_last;

    const int tid  = threadIdx.x;
    const int w    = tid >> 5, lane = tid & 31;
    const int gr   = lane >> 2, tc = lane & 3;
    const int ib   = blockIdx.x, js = blockIdx.y;
    const int i0   = ib * 256 + w * 32;

    // ---- coordinate A fragments (fp16 split), rows gr+8q, q=0..3 ----
    u32 pa[2][4];
    {
        float xh[4], xl[4], zh[4], zl[4], th[4], tl[4];
#pragma unroll
        for (int q = 0; q < 4; q++) {
            const int row = i0 + gr + q * 8;
            const float xv = x[row], zv = z[row], tv = t[row];
            xh[q] = __half2float(__float2half_rn(xv)); xl[q] = xv - xh[q];
            zh[q] = __half2float(__float2half_rn(zv)); zl[q] = zv - zh[q];
            th[q] = __half2float(__float2half_rn(tv)); tl[q] = tv - th[q];
        }
#pragma unroll
        for (int mt = 0; mt < 2; mt++)
#pragma unroll
            for (int qq = 0; qq < 2; qq++) {
                const int q = mt * 2 + qq;
                u32 lop, hip;
                if (tc == 0)      { lop = f16pk(xh[q], xl[q]); hip = f16pk(th[q], 1.0f); }
                else if (tc == 1) { lop = f16pk(zh[q], zl[q]); hip = f16pk(1.0f, 0.0f); }
                else if (tc == 2) { lop = f16pk(th[q], tl[q]); hip = 0u; }
                else              { lop = f16pk(xh[q], zh[q]); hip = 0u; }
                pa[mt][qq] = lop; pa[mt][2 + qq] = hip;
            }
    }

    float acc[2][3][4];
#pragma unroll
    for (int a = 0; a < 2; a++)
#pragma unroll
        for (int b = 0; b < 3; b++)
#pragma unroll
            for (int q = 0; q < 4; q++) acc[a][b][q] = 0.0f;

    const int ks0 = js * KSPB;
    const char* gB = (const char*)g_Bf + (u64)ks0 * 1536;
    const char* gA = (const char*)g_Af + (u64)ks0 * 512;

    // prologue prefetch stage 0
    {
        u32 dB = smem_u32(&sB[0][0]);
#pragma unroll
        for (int q = 0; q < 3; q++) cpa16(dB + tid * 16 + q * 4096, gB + tid * 16 + q * 4096);
        cpa16(smem_u32(&sA[0][0]) + tid * 16, gA + tid * 16);
        cpa_commit();
    }

    for (int st = 0; st < NSTAGE; st++) {
        const int buf = st & 1;
        if (st + 1 < NSTAGE) {
            const int nb = buf ^ 1;
            u32 dB = smem_u32(&sB[nb][0]);
            const char* sBg = gB + (u64)(st + 1) * (KS_STAGE * 1536);
#pragma unroll
            for (int q = 0; q < 3; q++) cpa16(dB + tid * 16 + q * 4096, sBg + tid * 16 + q * 4096);
            cpa16(smem_u32(&sA[nb][0]) + tid * 16, gA + (u64)(st + 1) * (KS_STAGE * 512) + tid * 16);
            cpa_commit();
            cpa_wait<1>();
        } else {
            cpa_wait<0>();
        }
        __syncthreads();

#pragma unroll 1
        for (int k = 0; k < KS_STAGE; k++) {
            // ---- arg GEMM: 4 MMAs give 16 exponent args per thread ----
            const uint4 af = *(const uint4*)(sA[buf] + k * 512 + lane * 16);
            u32 bA0[2] = { af.x, af.y };
            u32 bA1[2] = { af.z, af.w };
            float e00[4] = {0,0,0,0}, e01[4] = {0,0,0,0};
            float e10[4] = {0,0,0,0}, e11[4] = {0,0,0,0};
            mma_f16(e00, pa[0], bA0);
            mma_f16(e01, pa[0], bA1);
            mma_f16(e10, pa[1], bA0);
            mma_f16(e11, pa[1], bA1);

            // ---- ex2 -> moment A fragments (D layout == A layout) ----
            u32 ah[2][4];
            ah[0][0] = f16pk(ex2f(e00[0]), ex2f(e00[1]));
            ah[0][1] = f16pk(ex2f(e00[2]), ex2f(e00[3]));
            ah[0][2] = f16pk(ex2f(e01[0]), ex2f(e01[1]));
            ah[0][3] = f16pk(ex2f(e01[2]), ex2f(e01[3]));
            ah[1][0] = f16pk(ex2f(e10[0]), ex2f(e10[1]));
            ah[1][1] = f16pk(ex2f(e10[2]), ex2f(e10[3]));
            ah[1][2] = f16pk(ex2f(e11[0]), ex2f(e11[1]));
            ah[1][3] = f16pk(ex2f(e11[2]), ex2f(e11[3]));

            // ---- moment B frags (hi + lo) ----
            u32 bh[3][2], bl[3][2];
            const char* bp = sB[buf] + k * 1536 + lane * 8;
#pragma unroll
            for (int n = 0; n < 3; n++) {
                const uint2 vh = *(const uint2*)(bp + n * 256);
                const uint2 vl = *(const uint2*)(bp + 768 + n * 256);
                bh[n][0] = vh.x; bh[n][1] = vh.y;
                bl[n][0] = vl.x; bl[n][1] = vl.y;
            }

            // ---- 12 moment MMAs ----
#pragma unroll
            for (int mt = 0; mt < 2; mt++)
#pragma unroll
                for (int n = 0; n < 3; n++) {
                    mma_f16(acc[mt][n], ah[mt], bh[n]);
                    mma_f16(acc[mt][n], ah[mt], bl[n]);
                }
        }
        __syncthreads();
    }

    // ---- write moment partials ----
#pragma unroll
    for (int mt = 0; mt < 2; mt++)
#pragma unroll
        for (int n = 0; n < 3; n++) {
            const int row = i0 + mt * 16 + gr;
            const int col = n * 8 + 2 * tc;
            float2* d0 = (float2*)&g_part[((u64)js * NPTS + row) * NMOM + col];
            float2* d1 = (float2*)&g_part[((u64)js * NPTS + row + 8) * NMOM + col];
            *d0 = make_float2(acc[mt][n][0], acc[mt][n][1]);
            *d1 = make_float2(acc[mt][n][2], acc[mt][n][3]);
        }

    // ---- fused epilogue: last block of this i-group reduces + writes out ----
    __threadfence();
    __syncthreads();
    if (tid == 0) {
        const u32 old = atomicAdd(&g_cnt[ib], 1u);
        s_last = (old == JSPLIT - 1);
    }
    __syncthreads();
    if (!s_last) return;

    __threadfence();
    {
        const int i = ib * 256 + tid;
        float S[NMOM];
#pragma unroll
        for (int m = 0; m < NMOM; m++) S[m] = 0.0f;
#pragma unroll 4
        for (int jq = 0; jq < JSPLIT; jq++) {
            const float4* p = (const float4*)&g_part[((u64)jq * NPTS + i) * NMOM];
#pragma unroll
            for (int q = 0; q < 6; q++) {
                const float4 v = p[q];
                S[q * 4 + 0] += v.x; S[q * 4 + 1] += v.y;
                S[q * 4 + 2] += v.z; S[q * 4 + 3] += v.w;
            }
        }
        const float xi = x[i], zi = z[i], ti = t[i];
        const float ep = __expf(-0.5f * (xi * xi + zi * zi + ti * ti));
#pragma unroll
        for (int m = 0; m < 21; m++) S[m] *= ep;
        const float xx = xi * xi - 1.0f, zz = zi * zi - 1.0f;

        out[0  * NPTS + i] = S[10] - xi * S[9];
        out[1  * NPTS + i] = S[11] - zi * S[9];
        out[2  * NPTS + i] = S[12] - ti * S[9];
        out[3  * NPTS + i] = S[16] - xi * S[15];
        out[4  * NPTS + i] = S[17] - zi * S[15];
        out[5  * NPTS + i] = S[18] - ti * S[15];
        out[6  * NPTS + i] = S[4]  - xi * S[3];
        out[7  * NPTS + i] = S[5]  - zi * S[3];
        out[8  * NPTS + i] = S[6]  - ti * S[3];
        out[9  * NPTS + i] = S[1]  - xi * S[0];
        out[10 * NPTS + i] = S[2]  - zi * S[0];
        out[11 * NPTS + i] = S[13] - 2.0f * xi * S[10] + xx * S[9];
        out[12 * NPTS + i] = S[14] - 2.0f * zi * S[11] + zz * S[9];
        out[13 * NPTS + i] = S[19] - 2.0f * xi * S[16] + xx * S[15];
        out[14 * NPTS + i] = S[20] - 2.0f * zi * S[17] + zz * S[15];
        out[15 * NPTS + i] = S[7]  - 2.0f * xi * S[4]  + xx * S[3];
        out[16 * NPTS + i] = S[8]  - 2.0f * zi * S[5]  + zz * S[3];
    }
    __syncthreads();
    if (tid == 0) atomicExch(&g_cnt[ib], 0u);
}

extern "C" void kernel_launch(void* const* d_in, const int* in_sizes, int n_in,
                              void* d_out, int out_size)
{
    const float* x  = (const float*)d_in[0];
    const float* z  = (const float*)d_in[1];
    const float* t  = (const float*)d_in[2];
    const float* c  = (const float*)d_in[3];
    const float* v1 = (const float*)d_in[4];
    const float* v2 = (const float*)d_in[5];
    const float* v3 = (const float*)d_in[6];
    const float* v4 = (const float*)d_in[7];

    prep_all<<<(KSTEPS * 96) / 256, 256>>>(c, v1, v2, v3, v4);

    dim3 grid(IBLK, JSPLIT);                 // (24, 12) = 288 blocks
    rbf_mma<<<grid, 256>>>(x, z, t, (float*)d_out);
}

// round 9
// speedup vs baseline: 1.8312x; 1.0106x over previous
#include <cuda_runtime.h>
#include <cuda_fp16.h>
#include <cstdint>

typedef unsigned long long u64;
typedef unsigned int u32;

#define NPTS    6144
#define JSPLIT  12
#define IBLK    (NPTS / 128)          // 48 i-blocks (128 rows each)
#define KSTEPS  (NPTS / 16)           // 384 total k-steps (16 j each)
#define KSPB    (KSTEPS / JSPLIT)     // 32 k-steps per block
#define KS_STAGE 8
#define NSTAGE  (KSPB / KS_STAGE)     // 4
#define NMOM    24                    // moment columns (21 used)

// ---------------- device scratch ----------------
__device__ u32 g_Af[KSTEPS * 128];               // arg-GEMM B fragments
__device__ u64 g_Bf[KSTEPS * 2 * 3 * 32];        // moment B fragments (hi/lo)
__device__ float g_part[JSPLIT * NPTS * NMOM];   // moment partials
__device__ u32 g_cnt[IBLK];                      // zero-init; restored each call

// ---------------- helpers ----------------
__device__ __forceinline__ u32 smem_u32(const void* p) {
    u32 a; asm("{ .reg .u64 t; cvta.to.shared.u64 t, %1; cvt.u32.u64 %0, t; }" : "=r"(a) : "l"(p));
    return a;
}
__device__ __forceinline__ float ex2f(float a) {
    float r; asm("ex2.approx.ftz.f32 %0, %1;" : "=f"(r) : "f"(a)); return r;
}
// pack two f32 -> f16x2 (first arg in LOW 16 bits)
__device__ __forceinline__ u32 f16pk(float lo, float hi) {
    u32 d; asm("cvt.rn.f16x2.f32 %0, %1, %2;" : "=r"(d) : "f"(hi), "f"(lo)); return d;
}
__device__ __forceinline__ void cpa16(u32 saddr, const void* g) {
    asm volatile("cp.async.cg.shared.global [%0], [%1], 16;" :: "r"(saddr), "l"(g));
}
__device__ __forceinline__ void cpa_commit() { asm volatile("cp.async.commit_group;" ::: "memory"); }
template <int N> __device__ __forceinline__ void cpa_wait() {
    asm volatile("cp.async.wait_group %0;" :: "n"(N) : "memory");
}
__device__ __forceinline__ void mma_f16(float* c, const u32* a, const u32* b) {
    asm volatile(
        "mma.sync.aligned.m16n8k16.row.col.f32.f16.f16.f32 "
        "{%0,%1,%2,%3}, {%4,%5,%6,%7}, {%8,%9}, {%0,%1,%2,%3};"
        : "+f"(c[0]), "+f"(c[1]), "+f"(c[2]), "+f"(c[3])
        : "r"(a[0]), "r"(a[1]), "r"(a[2]), "r"(a[3]), "r"(b[0]), "r"(b[1]));
}

// ---------------- prep: arg fragments + moment fragments ----------------
__global__ void prep_all(const float* __restrict__ c,
                         const float* __restrict__ v1, const float* __restrict__ v2,
                         const float* __restrict__ v3, const float* __restrict__ v4)
{
    const int idx = blockIdx.x * blockDim.x + threadIdx.x;
    const float L2E = 1.4426950408889634f;

    if (idx < KSTEPS * 32) {
        const int lane = idx & 31, ks = idx >> 5;
        const int tc = lane & 3, gr = lane >> 2;
#pragma unroll
        for (int half = 0; half < 2; half++) {
            const int j = ks * 16 + half * 8 + gr;
            const float cx = c[3 * j], cz = c[3 * j + 1], ct = c[3 * j + 2];
            const float Cx = cx * L2E, Cz = cz * L2E, Ct = ct * L2E;
            const float kc = -0.5f * (cx * cx + cz * cz + ct * ct) * L2E;
            const float Cxh = __half2float(__float2half_rn(Cx)), Cxl = Cx - Cxh;
            const float Czh = __half2float(__float2half_rn(Cz)), Czl = Cz - Czh;
            const float Cth = __half2float(__float2half_rn(Ct)), Ctl = Ct - Cth;
            const float kch = __half2float(__float2half_rn(kc)), kcl = kc - kch;
            u32 b0, b1;
            if (tc == 0)      { b0 = f16pk(Cxh, Cxh); b1 = f16pk(Ctl, kch); }
            else if (tc == 1) { b0 = f16pk(Czh, Czh); b1 = f16pk(kcl, 0.f); }
            else if (tc == 2) { b0 = f16pk(Cth, Cth); b1 = 0u; }
            else              { b0 = f16pk(Cxl, Czl); b1 = 0u; }
            g_Af[ks * 128 + lane * 4 + half * 2 + 0] = b0;
            g_Af[ks * 128 + lane * 4 + half * 2 + 1] = b1;
        }
    }

    if (idx < KSTEPS * 96) {
        const int lane = idx & 31;
        const int n    = (idx >> 5) % 3;
        const int ks   = idx / 96;
        const int tc   = lane & 3, gr = lane >> 2;
        const int m    = n * 8 + gr;

        float u[4];
#pragma unroll
        for (int q = 0; q < 4; q++) {
            const int j = ks * 16 + 2 * tc + (q & 1) + ((q >> 1) << 3);
            float val = 0.0f;
            if (m < 21) {
                const float cx = c[3 * j], cz = c[3 * j + 1], ct = c[3 * j + 2];
                float vv, base;
                int r6;
                if (m < 3) { vv = v1[j]; r6 = m; }
                else {
                    const int g2 = (m - 3) / 6;
                    vv = (g2 == 0) ? v2[j] : (g2 == 1) ? v3[j] : v4[j];
                    r6 = (m - 3) % 6;
                }
                base = (r6 == 0) ? 1.0f : (r6 == 1) ? cx : (r6 == 2) ? cz :
                       (r6 == 3) ? ct   : (r6 == 4) ? cx * cx : cz * cz;
                val = base * vv;
            }
            u[q] = val;
        }
        const u32 b0h = f16pk(u[0], u[1]);
        const u32 b1h = f16pk(u[2], u[3]);
        const float h00 = __half2float(__ushort_as_half((unsigned short)(b0h & 0xFFFFu)));
        const float h01 = __half2float(__ushort_as_half((unsigned short)(b0h >> 16)));
        const float h10 = __half2float(__ushort_as_half((unsigned short)(b1h & 0xFFFFu)));
        const float h11 = __half2float(__ushort_as_half((unsigned short)(b1h >> 16)));
        const u32 b0l = f16pk(u[0] - h00, u[1] - h01);
        const u32 b1l = f16pk(u[2] - h10, u[3] - h11);
        g_Bf[(ks * 2 + 0) * 96 + n * 32 + lane] = ((u64)b1h << 32) | b0h;
        g_Bf[(ks * 2 + 1) * 96 + n * 32 + lane] = ((u64)b1l << 32) | b0l;
    }
}

// ---------------- main: one m16 tile per warp, 3 CTAs/SM target ----------------
__global__ __launch_bounds__(256, 3) void rbf_mma(
    const float* __restrict__ x, const float* __restrict__ z, const float* __restrict__ t,
    float* __restrict__ out)
{
    __shared__ __align__(16) char sB[2][KS_STAGE * 1536];   // 2 x 12KB moment frags
    __shared__ __align__(16) char sA[2][KS_STAGE * 512];    // 2 x 4KB  arg frags
    __shared__ int s_last;

    const int tid  = threadIdx.x;
    const int w    = tid >> 5, lane = tid & 31;
    const int gr   = lane >> 2, tc = lane & 3;
    const int ib   = blockIdx.x, js = blockIdx.y;
    const int i0   = ib * 128 + w * 16;      // this warp's 16 rows

    // ---- coordinate A fragment (fp16 split): a0,a1 = lo-parts rows gr/gr+8;
    //      a2,a3 = hi-parts rows gr/gr+8 ----
    u32 pa[4];
    {
#pragma unroll
        for (int q = 0; q < 2; q++) {
            const int row = i0 + gr + q * 8;
            const float xv = x[row], zv = z[row], tv = t[row];
            const float xh = __half2float(__float2half_rn(xv)), xl = xv - xh;
            const float zh = __half2float(__float2half_rn(zv)), zl = zv - zh;
            const float th = __half2float(__float2half_rn(tv)), tl = tv - th;
            u32 lop, hip;
            if (tc == 0)      { lop = f16pk(xh, xl); hip = f16pk(th, 1.0f); }
            else if (tc == 1) { lop = f16pk(zh, zl); hip = f16pk(1.0f, 0.0f); }
            else if (tc == 2) { lop = f16pk(th, tl); hip = 0u; }
            else              { lop = f16pk(xh, zh); hip = 0u; }
            pa[q] = lop; pa[2 + q] = hip;
        }
    }

    float acc[3][4];
#pragma unroll
    for (int b = 0; b < 3; b++)
#pragma unroll
        for (int q = 0; q < 4; q++) acc[b][q] = 0.0f;

    const int ks0 = js * KSPB;
    const char* gB = (const char*)g_Bf + (u64)ks0 * 1536;
    const char* gA = (const char*)g_Af + (u64)ks0 * 512;

    // prologue prefetch stage 0
    {
        u32 dB = smem_u32(&sB[0][0]);
#pragma unroll
        for (int q = 0; q < 3; q++) cpa16(dB + tid * 16 + q * 4096, gB + tid * 16 + q * 4096);
        cpa16(smem_u32(&sA[0][0]) + tid * 16, gA + tid * 16);
        cpa_commit();
    }

    for (int st = 0; st < NSTAGE; st++) {
        const int buf = st & 1;
        if (st + 1 < NSTAGE) {
            const int nb = buf ^ 1;
            u32 dB = smem_u32(&sB[nb][0]);
            const char* sBg = gB + (u64)(st + 1) * (KS_STAGE * 1536);
#pragma unroll
            for (int q = 0; q < 3; q++) cpa16(dB + tid * 16 + q * 4096, sBg + tid * 16 + q * 4096);
            cpa16(smem_u32(&sA[nb][0]) + tid * 16, gA + (u64)(st + 1) * (KS_STAGE * 512) + tid * 16);
            cpa_commit();
            cpa_wait<1>();
        } else {
            cpa_wait<0>();
        }
        __syncthreads();

#pragma unroll 1
        for (int k = 0; k < KS_STAGE; k++) {
            // ---- arg GEMM: 2 MMAs -> 8 exponent args per thread ----
            const uint4 af = *(const uint4*)(sA[buf] + k * 512 + lane * 16);
            u32 bA0[2] = { af.x, af.y };
            u32 bA1[2] = { af.z, af.w };
            float e0[4] = {0, 0, 0, 0}, e1[4] = {0, 0, 0, 0};
            mma_f16(e0, pa, bA0);
            mma_f16(e1, pa, bA1);

            // ---- ex2 -> moment A fragment ----
            u32 ah[4];
            ah[0] = f16pk(ex2f(e0[0]), ex2f(e0[1]));
            ah[1] = f16pk(ex2f(e0[2]), ex2f(e0[3]));
            ah[2] = f16pk(ex2f(e1[0]), ex2f(e1[1]));
            ah[3] = f16pk(ex2f(e1[2]), ex2f(e1[3]));

            // ---- moment B frags (hi + lo) ----
            const char* bp = sB[buf] + k * 1536 + lane * 8;
#pragma unroll
            for (int n = 0; n < 3; n++) {
                const uint2 vh = *(const uint2*)(bp + n * 256);
                const uint2 vl = *(const uint2*)(bp + 768 + n * 256);
                const u32 bh[2] = { vh.x, vh.y };
                const u32 bl[2] = { vl.x, vl.y };
                mma_f16(acc[n], ah, bh);
                mma_f16(acc[n], ah, bl);
            }
        }
        __syncthreads();
    }

    // ---- write moment partials ----
#pragma unroll
    for (int n = 0; n < 3; n++) {
        const int row = i0 + gr;
        const int col = n * 8 + 2 * tc;
        float2* d0 = (float2*)&g_part[((u64)js * NPTS + row) * NMOM + col];
        float2* d1 = (float2*)&g_part[((u64)js * NPTS + row + 8) * NMOM + col];
        *d0 = make_float2(acc[n][0], acc[n][1]);
        *d1 = make_float2(acc[n][2], acc[n][3]);
    }

    // ---- fused epilogue: last block of this i-group reduces + writes out ----
    __threadfence();
    __syncthreads();
    if (tid == 0) {
        const u32 old = atomicAdd(&g_cnt[ib], 1u);
        s_last = (old == JSPLIT - 1);
    }
    __syncthreads();
    if (!s_last) return;

    __threadfence();
    if (tid < 128) {
        const int i = ib * 128 + tid;
        float S[NMOM];
#pragma unroll
        for (int m = 0; m < NMOM; m++) S[m] = 0.0f;
#pragma unroll 4
        for (int jq = 0; jq < JSPLIT; jq++) {
            const float4* p = (const float4*)&g_part[((u64)jq * NPTS + i) * NMOM];
#pragma unroll
            for (int q = 0; q < 6; q++) {
                const float4 v = p[q];
                S[q * 4 + 0] += v.x; S[q * 4 + 1] += v.y;
                S[q * 4 + 2] += v.z; S[q * 4 + 3] += v.w;
            }
        }
        const float xi = x[i], zi = z[i], ti = t[i];
        const float ep = __expf(-0.5f * (xi * xi + zi * zi + ti * ti));
#pragma unroll
        for (int m = 0; m < 21; m++) S[m] *= ep;
        const float xx = xi * xi - 1.0f, zz = zi * zi - 1.0f;

        out[0  * NPTS + i] = S[10] - xi * S[9];
        out[1  * NPTS + i] = S[11] - zi * S[9];
        out[2  * NPTS + i] = S[12] - ti * S[9];
        out[3  * NPTS + i] = S[16] - xi * S[15];
        out[4  * NPTS + i] = S[17] - zi * S[15];
        out[5  * NPTS + i] = S[18] - ti * S[15];
        out[6  * NPTS + i] = S[4]  - xi * S[3];
        out[7  * NPTS + i] = S[5]  - zi * S[3];
        out[8  * NPTS + i] = S[6]  - ti * S[3];
        out[9  * NPTS + i] = S[1]  - xi * S[0];
        out[10 * NPTS + i] = S[2]  - zi * S[0];
        out[11 * NPTS + i] = S[13] - 2.0f * xi * S[10] + xx * S[9];
        out[12 * NPTS + i] = S[14] - 2.0f * zi * S[11] + zz * S[9];
        out[13 * NPTS + i] = S[19] - 2.0f * xi * S[16] + xx * S[15];
        out[14 * NPTS + i] = S[20] - 2.0f * zi * S[17] + zz * S[15];
        out[15 * NPTS + i] = S[7]  - 2.0f * xi * S[4]  + xx * S[3];
        out[16 * NPTS + i] = S[8]  - 2.0f * zi * S[5]  + zz * S[3];
    }
    __syncthreads();
    if (tid == 0) atomicExch(&g_cnt[ib], 0u);
}

extern "C" void kernel_launch(void* const* d_in, const int* in_sizes, int n_in,
                              void* d_out, int out_size)
{
    const float* x  = (const float*)d_in[0];
    const float* z  = (const float*)d_in[1];
    const float* t  = (const float*)d_in[2];
    const float* c  = (const float*)d_in[3];
    const float* v1 = (const float*)d_in[4];
    const float* v2 = (const float*)d_in[5];
    const float* v3 = (const float*)d_in[6];
    const float* v4 = (const float*)d_in[7];

    prep_all<<<(KSTEPS * 96) / 256, 256>>>(c, v1, v2, v3, v4);

    dim3 grid(IBLK, JSPLIT);                 // (48, 12) = 576 blocks
    rbf_mma<<<grid, 256>>>(x, z, t, (float*)d_out);
}

// round 11
// speedup vs baseline: 1.8709x; 1.0217x over previous
#include <cuda_runtime.h>
#include <cuda_fp16.h>
#include <cstdint>

typedef unsigned long long u64;
typedef unsigned int u32;

#define NPTS    6144
#define JSPLIT  12
#define IBLK    (NPTS / 128)          // 48 i-blocks (128 rows each)
#define KSTEPS  (NPTS / 16)           // 384 total k-steps (16 j each)
#define KSPB    (KSTEPS / JSPLIT)     // 32 k-steps per block
#define KS_STAGE 8
#define NSTAGE  (KSPB / KS_STAGE)     // 4
#define NMOM    24                    // moment columns (21 used)

// ---------------- device scratch ----------------
__device__ u32 g_Af[KSTEPS * 128];               // arg-GEMM B fragments (512B/ks)
__device__ u64 g_Bf[KSTEPS * 2 * 3 * 32];        // moment B fragments hi+lo (1536B/ks)
__device__ float g_part[JSPLIT * NPTS * NMOM];   // moment partials
__device__ u32 g_cnt[IBLK];                      // zero-init; restored each call

// ---------------- helpers ----------------
__device__ __forceinline__ u32 smem_u32(const void* p) {
    u32 a; asm("{ .reg .u64 t; cvta.to.shared.u64 t, %1; cvt.u32.u64 %0, t; }" : "=r"(a) : "l"(p));
    return a;
}
__device__ __forceinline__ float ex2f(float a) {
    float r; asm("ex2.approx.ftz.f32 %0, %1;" : "=f"(r) : "f"(a)); return r;
}
// pack two f32 -> f16x2 (first arg in LOW 16 bits)
__device__ __forceinline__ u32 f16pk(float lo, float hi) {
    u32 d; asm("cvt.rn.f16x2.f32 %0, %1, %2;" : "=r"(d) : "f"(hi), "f"(lo)); return d;
}
__device__ __forceinline__ void cpa16(u32 saddr, const void* g) {
    asm volatile("cp.async.cg.shared.global [%0], [%1], 16;" :: "r"(saddr), "l"(g));
}
__device__ __forceinline__ void cpa_commit() { asm volatile("cp.async.commit_group;" ::: "memory"); }
template <int N> __device__ __forceinline__ void cpa_wait() {
    asm volatile("cp.async.wait_group %0;" :: "n"(N) : "memory");
}
__device__ __forceinline__ void mma_f16(float* c, const u32* a, const u32* b) {
    asm volatile(
        "mma.sync.aligned.m16n8k16.row.col.f32.f16.f16.f32 "
        "{%0,%1,%2,%3}, {%4,%5,%6,%7}, {%8,%9}, {%0,%1,%2,%3};"
        : "+f"(c[0]), "+f"(c[1]), "+f"(c[2]), "+f"(c[3])
        : "r"(a[0]), "r"(a[1]), "r"(a[2]), "r"(a[3]), "r"(b[0]), "r"(b[1]));
}

// ---------------- prep: arg fragments + moment fragments (hi+lo) ----------------
__global__ void prep_all(const float* __restrict__ c,
                         const float* __restrict__ v1, const float* __restrict__ v2,
                         const float* __restrict__ v3, const float* __restrict__ v4)
{
    const int idx = blockIdx.x * blockDim.x + threadIdx.x;
    const float L2E = 1.4426950408889634f;

    if (idx < KSTEPS * 32) {
        const int lane = idx & 31, ks = idx >> 5;
        const int tc = lane & 3, gr = lane >> 2;
#pragma unroll
        for (int half = 0; half < 2; half++) {
            const int j = ks * 16 + half * 8 + gr;
            const float cx = c[3 * j], cz = c[3 * j + 1], ct = c[3 * j + 2];
            const float Cx = cx * L2E, Cz = cz * L2E, Ct = ct * L2E;
            const float kc = -0.5f * (cx * cx + cz * cz + ct * ct) * L2E;
            const float Cxh = __half2float(__float2half_rn(Cx)), Cxl = Cx - Cxh;
            const float Czh = __half2float(__float2half_rn(Cz)), Czl = Cz - Czh;
            const float Cth = __half2float(__float2half_rn(Ct)), Ctl = Ct - Cth;
            const float kch = __half2float(__float2half_rn(kc)), kcl = kc - kch;
            u32 b0, b1;
            if (tc == 0)      { b0 = f16pk(Cxh, Cxh); b1 = f16pk(Ctl, kch); }
            else if (tc == 1) { b0 = f16pk(Czh, Czh); b1 = f16pk(kcl, 0.f); }
            else if (tc == 2) { b0 = f16pk(Cth, Cth); b1 = 0u; }
            else              { b0 = f16pk(Cxl, Czl); b1 = 0u; }
            g_Af[ks * 128 + lane * 4 + half * 2 + 0] = b0;
            g_Af[ks * 128 + lane * 4 + half * 2 + 1] = b1;
        }
    }

    if (idx < KSTEPS * 96) {
        const int lane = idx & 31;
        const int n    = (idx >> 5) % 3;
        const int ks   = idx / 96;
        const int tc   = lane & 3, gr = lane >> 2;
        const int m    = n * 8 + gr;

        float u[4];
#pragma unroll
        for (int q = 0; q < 4; q++) {
            const int j = ks * 16 + 2 * tc + (q & 1) + ((q >> 1) << 3);
            float val = 0.0f;
            if (m < 21) {
                const float cx = c[3 * j], cz = c[3 * j + 1], ct = c[3 * j + 2];
                float vv, base;
                int r6;
                if (m < 3) { vv = v1[j]; r6 = m; }
                else {
                    const int g2 = (m - 3) / 6;
                    vv = (g2 == 0) ? v2[j] : (g2 == 1) ? v3[j] : v4[j];
                    r6 = (m - 3) % 6;
                }
                base = (r6 == 0) ? 1.0f : (r6 == 1) ? cx : (r6 == 2) ? cz :
                       (r6 == 3) ? ct   : (r6 == 4) ? cx * cx : cz * cz;
                val = base * vv;
            }
            u[q] = val;
        }
        const u32 b0h = f16pk(u[0], u[1]);
        const u32 b1h = f16pk(u[2], u[3]);
        const float h00 = __half2float(__ushort_as_half((unsigned short)(b0h & 0xFFFFu)));
        const float h01 = __half2float(__ushort_as_half((unsigned short)(b0h >> 16)));
        const float h10 = __half2float(__ushort_as_half((unsigned short)(b1h & 0xFFFFu)));
        const float h11 = __half2float(__ushort_as_half((unsigned short)(b1h >> 16)));
        const u32 b0l = f16pk(u[0] - h00, u[1] - h01);
        const u32 b1l = f16pk(u[2] - h10, u[3] - h11);
        g_Bf[(ks * 2 + 0) * 96 + n * 32 + lane] = ((u64)b1h << 32) | b0h;
        g_Bf[(ks * 2 + 1) * 96 + n * 32 + lane] = ((u64)b1l << 32) | b0l;
    }
}

// ---------------- main: pipelined arg-GEMM -> ex2 -> hi/lo moment GEMM ----------------
__global__ __launch_bounds__(256, 3) void rbf_mma(
    const float* __restrict__ x, const float* __restrict__ z, const float* __restrict__ t,
    float* __restrict__ out)
{
    __shared__ __align__(16) char sB[2][KS_STAGE * 1536];   // 2 x 12KB moment frags hi+lo
    __shared__ __align__(16) char sA[2][KS_STAGE * 512];    // 2 x 4KB  arg frags
    __shared__ int s_last;

    const int tid  = threadIdx.x;
    const int w    = tid >> 5, lane = tid & 31;
    const int gr   = lane >> 2, tc = lane & 3;
    const int ib   = blockIdx.x, js = blockIdx.y;
    const int i0   = ib * 128 + w * 16;

    // ---- coordinate A fragment (fp16 split) ----
    u32 pa[4];
#pragma unroll
    for (int q = 0; q < 2; q++) {
        const int row = i0 + gr + q * 8;
        const float xv = x[row], zv = z[row], tv = t[row];
        const float xh = __half2float(__float2half_rn(xv)), xl = xv - xh;
        const float zh = __half2float(__float2half_rn(zv)), zl = zv - zh;
        const float th = __half2float(__float2half_rn(tv)), tl = tv - th;
        u32 lop, hip;
        if (tc == 0)      { lop = f16pk(xh, xl); hip = f16pk(th, 1.0f); }
        else if (tc == 1) { lop = f16pk(zh, zl); hip = f16pk(1.0f, 0.0f); }
        else if (tc == 2) { lop = f16pk(th, tl); hip = 0u; }
        else              { lop = f16pk(xh, zh); hip = 0u; }
        pa[q] = lop; pa[2 + q] = hip;
    }

    float acc[3][4];
#pragma unroll
    for (int b = 0; b < 3; b++)
#pragma unroll
        for (int q = 0; q < 4; q++) acc[b][q] = 0.0f;

    const int ks0 = js * KSPB;
    const char* gB = (const char*)g_Bf + (u64)ks0 * 1536;
    const char* gA = (const char*)g_Af + (u64)ks0 * 512;

    // prologue prefetch stage 0
    {
        u32 dB = smem_u32(&sB[0][0]);
#pragma unroll
        for (int q = 0; q < 3; q++) cpa16(dB + tid * 16 + q * 4096, gB + tid * 16 + q * 4096);
        cpa16(smem_u32(&sA[0][0]) + tid * 16, gA + tid * 16);
        cpa_commit();
    }

    for (int st = 0; st < NSTAGE; st++) {
        const int buf = st & 1;
        if (st + 1 < NSTAGE) {
            const int nb = buf ^ 1;
            u32 dB = smem_u32(&sB[nb][0]);
            const char* nBg = gB + (u64)(st + 1) * (KS_STAGE * 1536);
#pragma unroll
            for (int q = 0; q < 3; q++) cpa16(dB + tid * 16 + q * 4096, nBg + tid * 16 + q * 4096);
            cpa16(smem_u32(&sA[nb][0]) + tid * 16, gA + (u64)(st + 1) * (KS_STAGE * 512) + tid * 16);
            cpa_commit();
            cpa_wait<1>();
        } else {
            cpa_wait<0>();
        }
        __syncthreads();

        // ---- stage prologue: arg MMA for k=0 ----
        float e0[4] = {0, 0, 0, 0}, e1[4] = {0, 0, 0, 0};
        {
            const uint4 af = *(const uint4*)(sA[buf] + lane * 16);
            const u32 b0[2] = { af.x, af.y };
            const u32 b1[2] = { af.z, af.w };
            mma_f16(e0, pa, b0);
            mma_f16(e1, pa, b1);
        }

#pragma unroll
        for (int k = 0; k < KS_STAGE; k++) {
            // ---- pack current args through ex2 ----
            u32 ah[4];
            ah[0] = f16pk(ex2f(e0[0]), ex2f(e0[1]));
            ah[1] = f16pk(ex2f(e0[2]), ex2f(e0[3]));
            ah[2] = f16pk(ex2f(e1[0]), ex2f(e1[1]));
            ah[3] = f16pk(ex2f(e1[2]), ex2f(e1[3]));

            // ---- issue arg MMA for k+1 (pipelined ahead of moment MMAs) ----
            float f0[4] = {0, 0, 0, 0}, f1[4] = {0, 0, 0, 0};
            if (k + 1 < KS_STAGE) {
                const uint4 af = *(const uint4*)(sA[buf] + (k + 1) * 512 + lane * 16);
                const u32 b0[2] = { af.x, af.y };
                const u32 b1[2] = { af.z, af.w };
                mma_f16(f0, pa, b0);
                mma_f16(f1, pa, b1);
            }

            // ---- 6 moment MMAs (hi + lo) ----
            const char* bp = sB[buf] + k * 1536 + lane * 8;
#pragma unroll
            for (int n = 0; n < 3; n++) {
                const uint2 vh = *(const uint2*)(bp + n * 256);
                const uint2 vl = *(const uint2*)(bp + 768 + n * 256);
                const u32 bh[2] = { vh.x, vh.y };
                const u32 bl[2] = { vl.x, vl.y };
                mma_f16(acc[n], ah, bh);
                mma_f16(acc[n], ah, bl);
            }

            // rotate (elided by full unroll register renaming)
#pragma unroll
            for (int q = 0; q < 4; q++) { e0[q] = f0[q]; e1[q] = f1[q]; }
        }
        __syncthreads();
    }

    // ---- write moment partials ----
#pragma unroll
    for (int n = 0; n < 3; n++) {
        const int row = i0 + gr;
        const int col = n * 8 + 2 * tc;
        float2* d0 = (float2*)&g_part[((u64)js * NPTS + row) * NMOM + col];
        float2* d1 = (float2*)&g_part[((u64)js * NPTS + row + 8) * NMOM + col];
        *d0 = make_float2(acc[n][0], acc[n][1]);
        *d1 = make_float2(acc[n][2], acc[n][3]);
    }

    // ---- fused epilogue: last block of this i-group reduces + writes out ----
    __threadfence();
    __syncthreads();
    if (tid == 0) {
        const u32 old = atomicAdd(&g_cnt[ib], 1u);
        s_last = (old == JSPLIT - 1);
    }
    __syncthreads();
    if (!s_last) return;

    __threadfence();
    if (tid < 128) {
        const int i = ib * 128 + tid;
        float S[NMOM];
#pragma unroll
        for (int m = 0; m < NMOM; m++) S[m] = 0.0f;
#pragma unroll 4
        for (int jq = 0; jq < JSPLIT; jq++) {
            const float4* p = (const float4*)&g_part[((u64)jq * NPTS + i) * NMOM];
#pragma unroll
            for (int q = 0; q < 6; q++) {
                const float4 v = p[q];
                S[q * 4 + 0] += v.x; S[q * 4 + 1] += v.y;
                S[q * 4 + 2] += v.z; S[q * 4 + 3] += v.w;
            }
        }
        const float xi = x[i], zi = z[i], ti = t[i];
        const float ep = __expf(-0.5f * (xi * xi + zi * zi + ti * ti));
#pragma unroll
        for (int m = 0; m < 21; m++) S[m] *= ep;
        const float xx = xi * xi - 1.0f, zz = zi * zi - 1.0f;

        out[0  * NPTS + i] = S[10] - xi * S[9];
        out[1  * NPTS + i] = S[11] - zi * S[9];
        out[2  * NPTS + i] = S[12] - ti * S[9];
        out[3  * NPTS + i] = S[16] - xi * S[15];
        out[4  * NPTS + i] = S[17] - zi * S[15];
        out[5  * NPTS + i] = S[18] - ti * S[15];
        out[6  * NPTS + i] = S[4]  - xi * S[3];
        out[7  * NPTS + i] = S[5]  - zi * S[3];
        out[8  * NPTS + i] = S[6]  - ti * S[3];
        out[9  * NPTS + i] = S[1]  - xi * S[0];
        out[10 * NPTS + i] = S[2]  - zi * S[0];
        out[11 * NPTS + i] = S[13] - 2.0f * xi * S[10] + xx * S[9];
        out[12 * NPTS + i] = S[14] - 2.0f * zi * S[11] + zz * S[9];
        out[13 * NPTS + i] = S[19] - 2.0f * xi * S[16] + xx * S[15];
        out[14 * NPTS + i] = S[20] - 2.0f * zi * S[17] + zz * S[15];
        out[15 * NPTS + i] = S[7]  - 2.0f * xi * S[4]  + xx * S[3];
        out[16 * NPTS + i] = S[8]  - 2.0f * zi * S[5]  + zz * S[3];
    }
    __syncthreads();
    if (tid == 0) atomicExch(&g_cnt[ib], 0u);
}

extern "C" void kernel_launch(void* const* d_in, const int* in_sizes, int n_in,
                              void* d_out, int out_size)
{
    const float* x  = (const float*)d_in[0];
    const float* z  = (const float*)d_in[1];
    const float* t  = (const float*)d_in[2];
    const float* c  = (const float*)d_in[3];
    const float* v1 = (const float*)d_in[4];
    const float* v2 = (const float*)d_in[5];
    const float* v3 = (const float*)d_in[6];
    const float* v4 = (const float*)d_in[7];

    prep_all<<<(KSTEPS * 96) / 256, 256>>>(c, v1, v2, v3, v4);

    dim3 grid(IBLK, JSPLIT);                 // (48, 12) = 576 blocks
    rbf_mma<<<grid, 256>>>(x, z, t, (float*)d_out);
}